// round 3
// baseline (speedup 1.0000x reference)
#include <cuda_runtime.h>
#include <cuda_bf16.h>
#include <cstdint>

// Top-1 MoE router (s=8192, e=64, capacity=160).
// Output (float32, concatenated): combine_weights [s,e,c], sec_mask [s,e,c] as 0/1,
// exp_counts [e]  -> out_size = 2*83886080 + 64 (confirmed in R2).
//
// Pipeline: route (argmax+softmax, per-token tables) -> select (per-expert top-CAP
// by rand, writes loc per kept token + counts) -> fused fill (writes both big
// regions with STG.128, value inserted inline; no memset, no scatter pass).

#define S 8192
#define E 64
#define CAP 160
#define CW_N 83886080LL  // S*E*CAP

// ---- device scratch (zero-init BSS; g_cnt re-zeroed by select each call) ----
__device__ int   g_cnt[E];
__device__ int   g_list[E][S];   // token ids per expert (order nondeterministic)
__device__ float g_prob[S];      // softmax prob at argmax expert
__device__ int   g_tok_ex[S];    // argmax expert per token
__device__ int   g_tok_loc[S];   // capacity slot if kept, else -1
__device__ unsigned char g_kept[E][S];  // fallback flags (large-n path)

// ---------------------------------------------------------------
// One warp per token: argmax over 64 experts (tie -> lowest index),
// softmax prob at argmax = 1 / sum(exp(x - max)). Also resets tok_loc.
__global__ void route_kernel(const float* __restrict__ x) {
    int token = blockIdx.x * (blockDim.x / 32) + (threadIdx.x >> 5);
    if (token >= S) return;
    int lane = threadIdx.x & 31;
    const float* row = x + (long long)token * E;
    float v0 = row[lane];
    float v1 = row[lane + 32];

    float bv; int bi;
    if (v1 > v0) { bv = v1; bi = lane + 32; } else { bv = v0; bi = lane; }
    #pragma unroll
    for (int o = 16; o; o >>= 1) {
        float ov = __shfl_xor_sync(0xffffffffu, bv, o);
        int   oi = __shfl_xor_sync(0xffffffffu, bi, o);
        if (ov > bv || (ov == bv && oi < bi)) { bv = ov; bi = oi; }
    }
    float s = __expf(v0 - bv) + __expf(v1 - bv);
    #pragma unroll
    for (int o = 16; o; o >>= 1) s += __shfl_xor_sync(0xffffffffu, s, o);

    if (lane == 0) {
        g_prob[token]    = 1.0f / s;
        g_tok_ex[token]  = bi;
        g_tok_loc[token] = -1;   // reset each call (deterministic)
        int slot = atomicAdd(&g_cnt[bi], 1);
        g_list[bi][slot] = token;
    }
}

// One block per expert: top-CAP by rand (tie -> lower token index, matching
// jax.lax.top_k), loc = rank by token index among kept. Writes g_tok_loc and
// exp_counts; re-zeroes g_cnt for the next call.
#define MAXN 2048
__global__ void select_kernel(const float* __restrict__ rnd,
                              float* __restrict__ out,
                              long long counts_off) {
    int e = blockIdx.x;
    int n = g_cnt[e];

    __shared__ float sr[MAXN];
    __shared__ int   st[MAXN];
    __shared__ unsigned char sk[MAXN];

    if (n <= MAXN) {
        for (int i = threadIdx.x; i < n; i += blockDim.x) {
            int t = g_list[e][i];
            st[i] = t;
            sr[i] = rnd[(long long)t * E + e];
        }
        __syncthreads();
        for (int i = threadIdx.x; i < n; i += blockDim.x) {
            float rj = sr[i]; int tj = st[i];
            int rank = 0;
            for (int k = 0; k < n; k++) {
                float rk = sr[k];
                rank += (rk > rj) || (rk == rj && st[k] < tj);
            }
            sk[i] = (rank < CAP) ? 1 : 0;
        }
        __syncthreads();
        for (int i = threadIdx.x; i < n; i += blockDim.x) {
            if (!sk[i]) continue;
            int tj = st[i];
            int loc = 0;
            for (int k = 0; k < n; k++) loc += (sk[k] && (st[k] < tj)) ? 1 : 0;
            g_tok_loc[tj] = loc;
        }
    } else {
        // robust fallback for pathological counts (> MAXN)
        for (int i = threadIdx.x; i < n; i += blockDim.x) {
            int tj = g_list[e][i];
            float rj = rnd[(long long)tj * E + e];
            int rank = 0;
            for (int k = 0; k < n; k++) {
                int tk = g_list[e][k];
                float rk = rnd[(long long)tk * E + e];
                rank += (rk > rj) || (rk == rj && tk < tj);
            }
            g_kept[e][i] = (rank < CAP) ? 1 : 0;
        }
        __syncthreads();
        for (int i = threadIdx.x; i < n; i += blockDim.x) {
            if (!g_kept[e][i]) continue;
            int tj = g_list[e][i];
            int loc = 0;
            for (int k = 0; k < n; k++)
                loc += (g_kept[e][k] && (g_list[e][k] < tj)) ? 1 : 0;
            g_tok_loc[tj] = loc;
        }
    }

    if (threadIdx.x == 0) {
        if (counts_off >= 0) out[counts_off + e] = (float)n;
        g_cnt[e] = 0;   // self-clean for next launch
    }
}

// Fused fill: one warp per (token, expert) row of CAP=160 floats (40 float4).
// Writes combine_weights and (optionally) sec_mask regions in one pass.
// Reads per row: 12 bytes of L2-resident table -> pure store-bound.
__global__ void fill_kernel(float* __restrict__ out, long long mask_off) {
    const int nwarp = (gridDim.x * blockDim.x) >> 5;
    int w = (blockIdx.x * blockDim.x + threadIdx.x) >> 5;
    int lane = threadIdx.x & 31;
    const long long R = (long long)S * E;

    for (long long row = w; row < R; row += nwarp) {
        int t = (int)(row >> 6);
        int e = (int)(row & 63);
        int pe   = __ldg(&g_tok_ex[t]);
        int ploc = __ldg(&g_tok_loc[t]);
        float pp = __ldg(&g_prob[t]);
        bool disp = (e == pe) && (ploc >= 0);
        int vq = disp ? (ploc >> 2) : -1;
        int vc = ploc & 3;

        float4* __restrict__ o0 = (float4*)(out + row * CAP);
        float4* __restrict__ o1 = (mask_off >= 0)
                                ? (float4*)(out + mask_off + row * CAP) : (float4*)0;
        #pragma unroll
        for (int j0 = 0; j0 < 2; j0++) {
            int j = lane + j0 * 32;
            if (j < 40) {
                float4 z = make_float4(0.f, 0.f, 0.f, 0.f);
                float4 m = z;
                if (j == vq) {
                    ((float*)&z)[vc] = pp;
                    ((float*)&m)[vc] = 1.0f;
                }
                o0[j] = z;
                if (o1) o1[j] = m;
            }
        }
    }
}

// ---------------------------------------------------------------
extern "C" void kernel_launch(void* const* d_in, const int* in_sizes, int n_in,
                              void* d_out, int out_size) {
    const float* x   = (const float*)d_in[0];
    const float* rnd = (const float*)d_in[1];
    float* out = (float*)d_out;

    long long osz = (long long)out_size;
    long long mask_off = -1, counts_off = -1;
    if (osz == CW_N) {
    } else if (osz == CW_N + E) {
        counts_off = CW_N;
    } else if (osz == 2 * CW_N) {
        mask_off = CW_N;
    } else if (osz == 2 * CW_N + E) {
        mask_off = CW_N;        // confirmed layout in R2
        counts_off = 2 * CW_N;
    } else {
        if (osz >= 2 * CW_N) mask_off = CW_N;
        if (((osz - E) % CW_N) == 0) counts_off = osz - E;
    }

    route_kernel<<<(S * 32 + 255) / 256, 256>>>(x);
    select_kernel<<<E, 256>>>(rnd, out, counts_off);
    fill_kernel<<<148 * 8, 256>>>(out, mask_off);
}

// round 4
// speedup vs baseline: 1.1199x; 1.1199x over previous
#include <cuda_runtime.h>
#include <cuda_bf16.h>
#include <cstdint>

// Top-1 MoE router (s=8192, e=64, capacity=160).
// Output (float32): combine_weights [s,e,c] | sec_mask [s,e,c] (0/1) | exp_counts [e]
// out_size = 2*83886080 + 64 (confirmed R2).
//
// Timeline (graph, fork/join):
//   origin:  memset(671MB) ─────────────┐
//   side:    route -> select ─(event)───┤
//   origin:                         scatter(<=16k stores + counts)
// Memset saturates DRAM writes (~6.7 TB/s, best engine per R3 post-mortem);
// compute overlaps fully under it.

#define S 8192
#define E 64
#define CAP 160
#define CW_N 83886080LL  // S*E*CAP

// ---- device scratch (zero-init BSS; g_cnt self-cleaned by select) ----
__device__ int   g_cnt[E];
__device__ int   g_excnt[E];            // counts snapshot for scatter
__device__ int   g_list[E][S];          // token ids per expert
__device__ float g_prob[S];             // softmax prob at argmax expert
__device__ int   g_tok_loc[S];          // (expert<<8)|loc if kept, else -1
__device__ unsigned char g_kept[E][S];  // fallback flags (large-n path)

// ---------------------------------------------------------------
// One warp per token: argmax over 64 experts (tie -> lowest index),
// prob = softmax value at argmax = 1/sum(exp(x-max)). Resets tok_loc.
__global__ void route_kernel(const float* __restrict__ x) {
    int token = blockIdx.x * (blockDim.x / 32) + (threadIdx.x >> 5);
    if (token >= S) return;
    int lane = threadIdx.x & 31;
    const float* row = x + (long long)token * E;
    float v0 = row[lane];
    float v1 = row[lane + 32];

    float bv; int bi;
    if (v1 > v0) { bv = v1; bi = lane + 32; } else { bv = v0; bi = lane; }
    #pragma unroll
    for (int o = 16; o; o >>= 1) {
        float ov = __shfl_xor_sync(0xffffffffu, bv, o);
        int   oi = __shfl_xor_sync(0xffffffffu, bi, o);
        if (ov > bv || (ov == bv && oi < bi)) { bv = ov; bi = oi; }
    }
    float s = __expf(v0 - bv) + __expf(v1 - bv);
    #pragma unroll
    for (int o = 16; o; o >>= 1) s += __shfl_xor_sync(0xffffffffu, s, o);

    if (lane == 0) {
        g_prob[token]    = 1.0f / s;
        g_tok_loc[token] = -1;
        int slot = atomicAdd(&g_cnt[bi], 1);
        g_list[bi][slot] = token;
    }
}

// One block per expert: top-CAP by rand (tie -> lower token idx, matching
// jax.lax.top_k); loc = rank by token idx among kept. Stores (e<<8)|loc.
#define MAXN 2048
__global__ void select_kernel(const float* __restrict__ rnd) {
    int e = blockIdx.x;
    int n = g_cnt[e];

    __shared__ float sr[MAXN];
    __shared__ int   st[MAXN];
    __shared__ unsigned char sk[MAXN];

    if (n <= MAXN) {
        for (int i = threadIdx.x; i < n; i += blockDim.x) {
            int t = g_list[e][i];
            st[i] = t;
            sr[i] = rnd[(long long)t * E + e];
        }
        __syncthreads();
        for (int i = threadIdx.x; i < n; i += blockDim.x) {
            float rj = sr[i]; int tj = st[i];
            int rank = 0;
            for (int k = 0; k < n; k++) {
                float rk = sr[k];
                rank += (rk > rj) || (rk == rj && st[k] < tj);
            }
            sk[i] = (rank < CAP) ? 1 : 0;
        }
        __syncthreads();
        for (int i = threadIdx.x; i < n; i += blockDim.x) {
            if (!sk[i]) continue;
            int tj = st[i];
            int loc = 0;
            for (int k = 0; k < n; k++) loc += (sk[k] && (st[k] < tj)) ? 1 : 0;
            g_tok_loc[tj] = (e << 8) | loc;
        }
    } else {
        for (int i = threadIdx.x; i < n; i += blockDim.x) {
            int tj = g_list[e][i];
            float rj = rnd[(long long)tj * E + e];
            int rank = 0;
            for (int k = 0; k < n; k++) {
                int tk = g_list[e][k];
                float rk = rnd[(long long)tk * E + e];
                rank += (rk > rj) || (rk == rj && tk < tj);
            }
            g_kept[e][i] = (rank < CAP) ? 1 : 0;
        }
        __syncthreads();
        for (int i = threadIdx.x; i < n; i += blockDim.x) {
            if (!g_kept[e][i]) continue;
            int tj = g_list[e][i];
            int loc = 0;
            for (int k = 0; k < n; k++)
                loc += (g_kept[e][k] && (g_list[e][k] < tj)) ? 1 : 0;
            g_tok_loc[tj] = (e << 8) | loc;
        }
    }

    if (threadIdx.x == 0) {
        g_excnt[e] = n;
        g_cnt[e] = 0;   // ready for next launch
    }
}

// After memset: one thread per token writes its (<=1) nonzero into each big
// region; first 64 threads also write exp_counts.
__global__ void scatter_kernel(float* __restrict__ out,
                               long long mask_off, long long counts_off) {
    int t = blockIdx.x * blockDim.x + threadIdx.x;
    if (t < E && counts_off >= 0) out[counts_off + t] = (float)g_excnt[t];
    if (t >= S) return;
    int v = g_tok_loc[t];
    if (v < 0) return;
    int e   = v >> 8;
    int loc = v & 255;
    long long base = (long long)t * (E * CAP) + (long long)e * CAP + loc;
    out[base] = g_prob[t];
    if (mask_off >= 0) out[mask_off + base] = 1.0f;
}

// ---------------------------------------------------------------
static cudaStream_t g_side = 0;
static cudaEvent_t  g_ev_fork = 0, g_ev_join = 0;

extern "C" void kernel_launch(void* const* d_in, const int* in_sizes, int n_in,
                              void* d_out, int out_size) {
    const float* x   = (const float*)d_in[0];
    const float* rnd = (const float*)d_in[1];
    float* out = (float*)d_out;

    if (!g_side) {
        cudaStreamCreateWithFlags(&g_side, cudaStreamNonBlocking);
        cudaEventCreateWithFlags(&g_ev_fork, cudaEventDisableTiming);
        cudaEventCreateWithFlags(&g_ev_join, cudaEventDisableTiming);
    }

    long long osz = (long long)out_size;
    long long mask_off = -1, counts_off = -1;
    if (osz == CW_N) {
    } else if (osz == CW_N + E) {
        counts_off = CW_N;
    } else if (osz == 2 * CW_N) {
        mask_off = CW_N;
    } else if (osz == 2 * CW_N + E) {
        mask_off = CW_N;
        counts_off = 2 * CW_N;
    } else {
        if (osz >= 2 * CW_N) mask_off = CW_N;
        if (((osz - E) % CW_N) == 0) counts_off = osz - E;
    }

    // fork: side stream computes routing while origin stream memsets 671MB
    cudaEventRecord(g_ev_fork, 0);
    cudaStreamWaitEvent(g_side, g_ev_fork, 0);

    route_kernel<<<(S * 32 + 255) / 256, 256, 0, g_side>>>(x);
    select_kernel<<<E, 256, 0, g_side>>>(rnd);
    cudaEventRecord(g_ev_join, g_side);

    cudaMemsetAsync(d_out, 0, (size_t)osz * sizeof(float), 0);

    // join, then scatter the sparse nonzeros
    cudaStreamWaitEvent(0, g_ev_join, 0);
    scatter_kernel<<<(S + 255) / 256, 256>>>(out, mask_off, counts_off);
}

// round 10
// speedup vs baseline: 1.1668x; 1.0419x over previous
#include <cuda_runtime.h>
#include <cuda_bf16.h>
#include <cstdint>

// Top-1 MoE router (s=8192, e=64, capacity=160).
// Output (float32): combine_weights [s,e,c] | sec_mask [s,e,c] (0/1) | exp_counts [e]
// out_size = 2*83886080 + 64 (confirmed R2).
//
// Serialized timeline (overlap regressed in R4 — memset is an SM kernel and
// loses bandwidth to concurrent work):
//   memset(671MB, ~99us, ~6.8TB/s) -> route(~3us) -> select_scatter(~4us)

#define S 8192
#define E 64
#define CAP 160
#define CW_N 83886080LL  // S*E*CAP

// ---- device scratch (no allocations allowed) ----
__device__ float g_prob[S];    // softmax prob at argmax expert
__device__ int   g_tok_ex[S];  // argmax expert per token

// ---------------------------------------------------------------
// Thread-per-token: 16x LDG.128 (MLP=16), argmax (tie -> lowest index),
// prob = 1/sum(exp(x - max)). No shuffles, no atomics.
__global__ void route_kernel(const float* __restrict__ x) {
    int t = blockIdx.x * blockDim.x + threadIdx.x;
    if (t >= S) return;
    const float4* __restrict__ row = (const float4*)(x + (long long)t * E);

    float4 v[16];
    #pragma unroll
    for (int i = 0; i < 16; i++) v[i] = row[i];

    float bv = v[0].x; int bi = 0;
    #pragma unroll
    for (int i = 0; i < 16; i++) {
        float a[4] = {v[i].x, v[i].y, v[i].z, v[i].w};
        #pragma unroll
        for (int j = 0; j < 4; j++) {
            int idx = i * 4 + j;
            if (a[j] > bv) { bv = a[j]; bi = idx; }
        }
    }
    float s = 0.f;
    #pragma unroll
    for (int i = 0; i < 16; i++) {
        s += __expf(v[i].x - bv) + __expf(v[i].y - bv)
           + __expf(v[i].z - bv) + __expf(v[i].w - bv);
    }
    g_prob[t]   = 1.0f / s;
    g_tok_ex[t] = bi;
}

// One block per expert: scan g_tok_ex (L2-resident, int4 loads), compact to
// smem, top-CAP by rand (tie -> lower token idx, matching jax.lax.top_k),
// loc = rank by token idx among kept, scatter nonzeros + counts.
// Rank computations are order-independent, so nondeterministic compaction
// order is fine.
#define MAXN 2048
__global__ void select_scatter_kernel(const float* __restrict__ rnd,
                                      float* __restrict__ out,
                                      long long mask_off, long long counts_off) {
    int e = blockIdx.x;

    __shared__ int   cnt;
    __shared__ int   st[MAXN];
    __shared__ float sr[MAXN];
    __shared__ unsigned char sk[MAXN];

    if (threadIdx.x == 0) cnt = 0;
    __syncthreads();

    const int4* __restrict__ ex4 = (const int4*)g_tok_ex;
    for (int i = threadIdx.x; i < S / 4; i += blockDim.x) {
        int4 q = __ldg(&ex4[i]);
        int base = i * 4;
        if (q.x == e) { int p = atomicAdd(&cnt, 1); if (p < MAXN) st[p] = base; }
        if (q.y == e) { int p = atomicAdd(&cnt, 1); if (p < MAXN) st[p] = base + 1; }
        if (q.z == e) { int p = atomicAdd(&cnt, 1); if (p < MAXN) st[p] = base + 2; }
        if (q.w == e) { int p = atomicAdd(&cnt, 1); if (p < MAXN) st[p] = base + 3; }
    }
    __syncthreads();
    int n = cnt;
    int m = (n < MAXN) ? n : MAXN;

    for (int i = threadIdx.x; i < m; i += blockDim.x)
        sr[i] = __ldg(&rnd[(long long)st[i] * E + e]);
    __syncthreads();

    // rank by (rand desc, token idx asc); keep if rank < CAP
    for (int i = threadIdx.x; i < m; i += blockDim.x) {
        float rj = sr[i]; int tj = st[i];
        int rank = 0;
        for (int k = 0; k < m; k++) {
            float rk = sr[k];
            rank += (rk > rj) || (rk == rj && st[k] < tj);
        }
        sk[i] = (rank < CAP) ? 1 : 0;
    }
    __syncthreads();

    // loc = rank by token idx among kept; scatter
    for (int i = threadIdx.x; i < m; i += blockDim.x) {
        if (!sk[i]) continue;
        int tj = st[i];
        int loc = 0;
        for (int k = 0; k < m; k++) loc += (sk[k] && (st[k] < tj)) ? 1 : 0;
        long long base = (long long)tj * (E * CAP) + (long long)e * CAP + loc;
        out[base] = g_prob[tj];
        if (mask_off >= 0) out[mask_off + base] = 1.0f;
    }

    if (threadIdx.x == 0 && counts_off >= 0) out[counts_off + e] = (float)n;
}

// ---------------------------------------------------------------
extern "C" void kernel_launch(void* const* d_in, const int* in_sizes, int n_in,
                              void* d_out, int out_size) {
    const float* x   = (const float*)d_in[0];
    const float* rnd = (const float*)d_in[1];
    float* out = (float*)d_out;

    long long osz = (long long)out_size;
    long long mask_off = -1, counts_off = -1;
    if (osz == CW_N) {
    } else if (osz == CW_N + E) {
        counts_off = CW_N;
    } else if (osz == 2 * CW_N) {
        mask_off = CW_N;
    } else if (osz == 2 * CW_N + E) {
        mask_off = CW_N;        // confirmed layout
        counts_off = 2 * CW_N;
    } else {
        if (osz >= 2 * CW_N) mask_off = CW_N;
        if (((osz - E) % CW_N) == 0) counts_off = osz - E;
    }

    cudaMemsetAsync(d_out, 0, (size_t)osz * sizeof(float), 0);
    route_kernel<<<(S + 255) / 256, 256>>>(x);
    select_scatter_kernel<<<E, 256>>>(rnd, out, mask_off, counts_off);
}

// round 12
// speedup vs baseline: 1.2771x; 1.0945x over previous
#include <cuda_runtime.h>
#include <cuda_bf16.h>
#include <cstdint>

// Top-1 MoE router (s=8192, e=64, capacity=160).
// Output (float32): combine_weights [s,e,c] | sec_mask [s,e,c] (0/1) | exp_counts [e]
// out_size = 2*83886080 + 64 (confirmed R2).
//
// Timeline: memset(671MB ~97us) -> route(flat + atomic compaction ~5us)
//           -> select (no scan; fast path n<=CAP skips rand ranking ~3us)

#define S 8192
#define E 64
#define CAP 160
#define CW_N 83886080LL  // S*E*CAP

// ---- device scratch (zero-init BSS; g_cnt self-cleaned by select) ----
__device__ int   g_cnt[E];
__device__ int   g_list[E][S];   // token ids per expert (order nondeterministic)
__device__ float g_prob[S];      // softmax prob at argmax expert

// ---------------------------------------------------------------
// Thread-per-token: 16x LDG.128 (MLP=16), argmax (tie -> lowest index),
// prob = 1/sum(exp(x - max)); compact into per-expert lists via atomics.
__global__ void route_kernel(const float* __restrict__ x) {
    int t = blockIdx.x * blockDim.x + threadIdx.x;
    if (t >= S) return;
    const float4* __restrict__ row = (const float4*)(x + (long long)t * E);

    float4 v[16];
    #pragma unroll
    for (int i = 0; i < 16; i++) v[i] = row[i];

    float bv = v[0].x; int bi = 0;
    #pragma unroll
    for (int i = 0; i < 16; i++) {
        float a[4] = {v[i].x, v[i].y, v[i].z, v[i].w};
        #pragma unroll
        for (int j = 0; j < 4; j++) {
            int idx = i * 4 + j;
            if (a[j] > bv) { bv = a[j]; bi = idx; }
        }
    }
    float s = 0.f;
    #pragma unroll
    for (int i = 0; i < 16; i++) {
        s += __expf(v[i].x - bv) + __expf(v[i].y - bv)
           + __expf(v[i].z - bv) + __expf(v[i].w - bv);
    }
    g_prob[t] = 1.0f / s;
    int slot = atomicAdd(&g_cnt[bi], 1);
    g_list[bi][slot] = t;
}

// One block per expert, no scan: list already compacted.
// Fast path (n <= CAP): every assigned token kept -> loc = rank of token idx
// among assigned (order-independent). Rare n > CAP: rank by (rand desc,
// token idx asc) per jax.lax.top_k, keep rank<CAP, loc = idx-rank among kept.
#define MAXN 2048
__global__ void select_scatter_kernel(const float* __restrict__ rnd,
                                      float* __restrict__ out,
                                      long long mask_off, long long counts_off) {
    int e = blockIdx.x;
    int n = g_cnt[e];
    int m = (n < MAXN) ? n : MAXN;

    __shared__ int   st[MAXN];
    __shared__ float sr[MAXN];
    __shared__ unsigned char sk[MAXN];

    for (int i = threadIdx.x; i < m; i += blockDim.x)
        st[i] = g_list[e][i];
    __syncthreads();

    if (n <= CAP) {
        // all kept: loc = #{assigned tokens with smaller index}
        for (int i = threadIdx.x; i < m; i += blockDim.x) {
            int tj = st[i];
            int loc = 0;
            for (int k = 0; k < m; k++) loc += (st[k] < tj) ? 1 : 0;
            long long base = (long long)tj * (E * CAP) + (long long)e * CAP + loc;
            out[base] = g_prob[tj];
            if (mask_off >= 0) out[mask_off + base] = 1.0f;
        }
    } else {
        for (int i = threadIdx.x; i < m; i += blockDim.x)
            sr[i] = __ldg(&rnd[(long long)st[i] * E + e]);
        __syncthreads();
        for (int i = threadIdx.x; i < m; i += blockDim.x) {
            float rj = sr[i]; int tj = st[i];
            int rank = 0;
            for (int k = 0; k < m; k++) {
                float rk = sr[k];
                rank += (rk > rj) || (rk == rj && st[k] < tj);
            }
            sk[i] = (rank < CAP) ? 1 : 0;
        }
        __syncthreads();
        for (int i = threadIdx.x; i < m; i += blockDim.x) {
            if (!sk[i]) continue;
            int tj = st[i];
            int loc = 0;
            for (int k = 0; k < m; k++) loc += (sk[k] && (st[k] < tj)) ? 1 : 0;
            long long base = (long long)tj * (E * CAP) + (long long)e * CAP + loc;
            out[base] = g_prob[tj];
            if (mask_off >= 0) out[mask_off + base] = 1.0f;
        }
    }

    if (threadIdx.x == 0) {
        if (counts_off >= 0) out[counts_off + e] = (float)n;
        g_cnt[e] = 0;   // self-clean for next call (deterministic)
    }
}

// ---------------------------------------------------------------
extern "C" void kernel_launch(void* const* d_in, const int* in_sizes, int n_in,
                              void* d_out, int out_size) {
    const float* x   = (const float*)d_in[0];
    const float* rnd = (const float*)d_in[1];
    float* out = (float*)d_out;

    long long osz = (long long)out_size;
    long long mask_off = -1, counts_off = -1;
    if (osz == CW_N) {
    } else if (osz == CW_N + E) {
        counts_off = CW_N;
    } else if (osz == 2 * CW_N) {
        mask_off = CW_N;
    } else if (osz == 2 * CW_N + E) {
        mask_off = CW_N;        // confirmed layout
        counts_off = 2 * CW_N;
    } else {
        if (osz >= 2 * CW_N) mask_off = CW_N;
        if (((osz - E) % CW_N) == 0) counts_off = osz - E;
    }

    cudaMemsetAsync(d_out, 0, (size_t)osz * sizeof(float), 0);
    route_kernel<<<(S + 255) / 256, 256>>>(x);
    select_scatter_kernel<<<E, 256>>>(rnd, out, mask_off, counts_off);
}